// round 15
// baseline (speedup 1.0000x reference)
#include <cuda_runtime.h>
#include <cuda_bf16.h>

#define NS    125
#define NW    5
#define NZ    625
#define NR    500
#define DDIM  8192
#define NQ    2048
#define MAXIT 20
#define NCHEB 12
#define NT    1024

// Chebyshev interval for block-Jacobi-preconditioned reduced system
#define CH_THETA  1.0f
#define CH_DELTA  0.38f
#define CH_SIGMA1 (CH_THETA / CH_DELTA)

__device__ float g_Kslice[32][16384];
__device__ float g_K[16384];
__device__ float g_z[NZ];
__device__ float g_compat[NQ * 128];   // compat[q][i] = dot(S_i, Q_q), i padded to 128

// 5x4 orthonormal basis of {v in R^5 : sum v = 0}
__constant__ float cZ[5][4] = {
    { 0.44721360f,  0.44721360f,  0.44721360f,  0.44721360f},
    { 0.63819660f, -0.36180340f, -0.36180340f, -0.36180340f},
    {-0.36180340f,  0.63819660f, -0.36180340f, -0.36180340f},
    {-0.36180340f, -0.36180340f,  0.63819660f, -0.36180340f},
    {-0.36180340f, -0.36180340f, -0.36180340f,  0.63819660f}};

// ================= K = S S^T : 32 k-slices, one 128x128 tile each =================
__global__ void __launch_bounds__(1024, 1) k_gemmK(const float* __restrict__ sup) {
    __shared__ float St[32][128];
    const int t = threadIdx.x;
    const int ty = t >> 5, tx = t & 31;
    const int frow = t >> 3, fc4 = t & 7;
    float acc[4][4];
#pragma unroll
    for (int a = 0; a < 4; a++)
#pragma unroll
        for (int b = 0; b < 4; b++) acc[a][b] = 0.f;

    const int kbase = blockIdx.x * 256;
    for (int k0 = kbase; k0 < kbase + 256; k0 += 32) {
        float4 sv = make_float4(0.f, 0.f, 0.f, 0.f);
        if (frow < NS) sv = *(const float4*)(sup + (long)frow * DDIM + k0 + 4 * fc4);
        __syncthreads();
        St[4 * fc4 + 0][frow] = sv.x;
        St[4 * fc4 + 1][frow] = sv.y;
        St[4 * fc4 + 2][frow] = sv.z;
        St[4 * fc4 + 3][frow] = sv.w;
        __syncthreads();
#pragma unroll
        for (int kk = 0; kk < 32; kk++) {
            float4 a4 = *(float4*)&St[kk][4 * ty];
            float4 b4 = *(float4*)&St[kk][4 * tx];
            float av[4] = {a4.x, a4.y, a4.z, a4.w};
            float bv[4] = {b4.x, b4.y, b4.z, b4.w};
#pragma unroll
            for (int mi = 0; mi < 4; mi++)
#pragma unroll
                for (int ni = 0; ni < 4; ni++) acc[mi][ni] += av[mi] * bv[ni];
        }
    }
#pragma unroll
    for (int mi = 0; mi < 4; mi++)
#pragma unroll
        for (int ni = 0; ni < 4; ni++)
            g_Kslice[blockIdx.x][(4 * ty + mi) * 128 + 4 * tx + ni] = acc[mi][ni];
}

__global__ void k_reduceK() {
    int idx = blockIdx.x * blockDim.x + threadIdx.x;
    float a = 0.f;
#pragma unroll
    for (int s = 0; s < 32; s++) a += g_Kslice[s][idx];
    g_K[idx] = a;
}

// ================= block reductions =================
__device__ __forceinline__ float blkSum(float v, float* sc) {
#pragma unroll
    for (int o = 16; o; o >>= 1) v += __shfl_down_sync(0xffffffffu, v, o);
    if ((threadIdx.x & 31) == 0) sc[threadIdx.x >> 5] = v;
    __syncthreads();
    if (threadIdx.x < 32) {
        float x = sc[threadIdx.x];
#pragma unroll
        for (int o = 16; o; o >>= 1) x += __shfl_down_sync(0xffffffffu, x, o);
        if (threadIdx.x == 0) sc[32] = x;
    }
    __syncthreads();
    float r = sc[32];
    __syncthreads();
    return r;
}

__device__ __forceinline__ float blkMin(float v, float* sc) {
#pragma unroll
    for (int o = 16; o; o >>= 1) v = fminf(v, __shfl_down_sync(0xffffffffu, v, o));
    if ((threadIdx.x & 31) == 0) sc[threadIdx.x >> 5] = v;
    __syncthreads();
    if (threadIdx.x < 32) {
        float x = sc[threadIdx.x];
#pragma unroll
        for (int o = 16; o; o >>= 1) x = fminf(x, __shfl_down_sync(0xffffffffu, x, o));
        if (threadIdx.x == 0) sc[32] = x;
    }
    __syncthreads();
    float r = sc[32];
    __syncthreads();
    return r;
}

// K matvec, K register-resident: thread t<1000 holds K[t%125][16*(t/125)..+15]
template <int NC>
__device__ __forceinline__ void kmatvec(const float (&kr)[16], int i_, int seg, bool act,
                                        const float* V, float* Y, float* part) {
    if (act) {
        float ps[NC];
#pragma unroll
        for (int c = 0; c < NC; c++) ps[c] = 0.f;
        const int jb = seg * 16;
#pragma unroll
        for (int k = 0; k < 16; k++) {
            float f = kr[k];
#pragma unroll
            for (int c = 0; c < NC; c++) ps[c] += f * V[(jb + k) * NC + c];
        }
#pragma unroll
        for (int c = 0; c < NC; c++) part[(c * 8 + seg) * 128 + i_] = ps[c];
    }
    __syncthreads();
    for (int u = threadIdx.x; u < NS * NC; u += NT) {
        int c = u / NS, ii = u - c * NS;
        float acc = 0.f;
#pragma unroll
        for (int g = 0; g < 8; g++) acc += part[(c * 8 + g) * 128 + ii];
        Y[ii * NC + c] = acc;
    }
    __syncthreads();
}

// smem float offsets (IPM CTA)
#define O_Z     0
#define O_S     640
#define O_LAM   1265
#define O_DD    1890
#define O_R2    2515
#define O_R3    3140
#define O_RHS   3765
#define O_CB    4390
#define O_DZ    5015
#define O_TV    5640
#define O_KT    5768
#define O_KD    5896
#define O_NU    6024
#define O_XS    6152
#define O_RS    6664
#define O_DS    7176
#define O_AP    7688
#define O_MINV  8200
#define O_BSM   10200
#define O_PART  12200
#define O_SC    17320
#define O_LB    17384
#define SMEM_FLOATS 17512
#define SMEM_BYTES  (SMEM_FLOATS * 4)

__global__ void __launch_bounds__(NT, 1)
k_ipm(const float* __restrict__ query, const int* __restrict__ lblg,
      float* __restrict__ out, int out_size) {
    extern __shared__ float sm[];
    const int t = threadIdx.x;

    // ---------------- sibling CTAs: compat = S . Q^T (hidden under the IPM) ----------------
    if (blockIdx.x != 0) {
        const float* sup = query + (long)NQ * DDIM * 0;  // placeholder, real pointer below
        // support pointer is passed via g_K? No — we re-derive: support is the SECOND big input.
        // We instead read S from global g_Ksup set in launch? Simpler: support passed via query+offset
        // is not possible; so support pointer comes in via lblg? No. We pass support as 'out'? No.
        // -> support is reachable: we stash it in constant? Use separate param below.
        // (this branch body replaced — see k_ipm2 wrapper note)
        return;
    }

    float* Z = sm + O_Z;     float* S = sm + O_S;     float* LAM = sm + O_LAM;
    float* DDv = sm + O_DD;  float* R2 = sm + O_R2;   float* R3 = sm + O_R3;
    float* RHS = sm + O_RHS; float* CB = sm + O_CB;   float* DZ = sm + O_DZ;
    float* TV = sm + O_TV;   float* KT = sm + O_KT;   float* KD = sm + O_KD;
    float* NU = sm + O_NU;   float* XS = sm + O_XS;   float* RS = sm + O_RS;
    float* DS = sm + O_DS;   float* AP = sm + O_AP;
    float* MINV = sm + O_MINV; float* BSM = sm + O_BSM; float* PART = sm + O_PART;
    float* SC = sm + O_SC;   int* LB = (int*)(sm + O_LB);

    const int i_ = t % NS, seg = t / NS;
    const bool act = (t < 1000);

    float kr[16];
#pragma unroll
    for (int k = 0; k < 16; k++) kr[k] = act ? g_K[i_ * 128 + seg * 16 + k] : 0.f;

    for (int u = t; u < 640; u += NT) Z[u] = 0.f;
    if (t < NZ)  { S[t] = 1.f; LAM[t] = 1.f; }
    if (t < 128) { NU[t] = 0.f; TV[t] = 0.f; }
    if (t < 512) { DS[t] = 0.f; }
    if (t < NS)  { KD[t] = g_K[t * 128 + t]; LB[t] = lblg[t]; }
    __syncthreads();

    for (int it = 0; it < MAXIT; it++) {
        // KZ (5 cols) -> DZ
        kmatvec<5>(kr, i_, seg, act, Z, DZ, PART);
        float mu = 0.1f * blkSum((t < NZ) ? S[t] * LAM[t] : 0.f, SC) * (1.f / 625.f);

        if (t < NZ) {
            int ii = t / NW, w = t - ii * NW;
            float e = (LB[ii] == w) ? -1.f : 0.f;
            float h = (LB[ii] == w) ? 0.1f : 0.f;
            float sv = S[t], lv = LAM[t], zv = Z[t];
            float r1 = (DZ[t] + zv) + e + lv + NU[ii];
            float r2v = zv + sv - h;
            float r3v = lv * sv - mu;
            R2[t] = r2v; R3[t] = r3v; DDv[t] = lv / sv;
            RHS[t] = -(r1 + (lv * r2v - r3v) / sv);
        }
        if (t < NS) {
            // particular solution and its K-image (free: K*TV = -0.2 * rowsum(KZ))
            TV[t] = -0.2f * (Z[t*5] + Z[t*5+1] + Z[t*5+2] + Z[t*5+3] + Z[t*5+4]);
            KT[t] = -0.2f * (DZ[t*5] + DZ[t*5+1] + DZ[t*5+2] + DZ[t*5+3] + DZ[t*5+4]);
        }
        __syncthreads();

        if (t < NZ) {
            int ii = t / NW;
            CB[t] = RHS[t] - KT[ii] - TV[ii] * (1.f + DDv[t]);  // c = rhs1 - H dz_p
        }
        if (t < NS) {
            float dd[5];
#pragma unroll
            for (int w = 0; w < NW; w++) dd[w] = DDv[t * NW + w];
            float M[4][4], Inv[4][4];
#pragma unroll
            for (int a = 0; a < 4; a++)
#pragma unroll
                for (int b = 0; b < 4; b++) {
                    float s2 = 0.f;
#pragma unroll
                    for (int w = 0; w < NW; w++) s2 += cZ[w][a] * dd[w] * cZ[w][b];
                    BSM[t * 16 + a * 4 + b] = s2;
                    M[a][b] = s2;
                    Inv[a][b] = (a == b) ? 1.f : 0.f;
                }
            float dg = KD[t] + 1.f;
#pragma unroll
            for (int a = 0; a < 4; a++) M[a][a] += dg;
#pragma unroll
            for (int k = 0; k < 4; k++) {
                float piv = 1.f / M[k][k];
#pragma unroll
                for (int c = 0; c < 4; c++) { M[k][c] *= piv; Inv[k][c] *= piv; }
#pragma unroll
                for (int r = 0; r < 4; r++) if (r != k) {
                    float f = M[r][k];
#pragma unroll
                    for (int c = 0; c < 4; c++) { M[r][c] -= f * M[k][c]; Inv[r][c] -= f * Inv[k][c]; }
                }
            }
#pragma unroll
            for (int a = 0; a < 4; a++)
#pragma unroll
                for (int b = 0; b < 4; b++) MINV[t * 16 + a * 4 + b] = Inv[a][b];
        }
        __syncthreads();

        // reduced rhs bq = Z^T c
        if (t < NR) {
            int ii = t / 4, a = t - ii * 4;
            float bv = 0.f;
#pragma unroll
            for (int w = 0; w < NW; w++) bv += cZ[w][a] * CB[ii * NW + w];
            RS[t] = bv; XS[t] = 0.f;
        }
        __syncthreads();
        // d0 = M^-1 r0 / theta   (theta = 1)
        if (t < NR) {
            int ii = t / 4, a = t - ii * 4;
            float zz = 0.f;
#pragma unroll
            for (int b = 0; b < 4; b++) zz += MINV[ii * 16 + a * 4 + b] * RS[ii * 4 + b];
            DS[t] = zz;
        }
        __syncthreads();

        // -------- preconditioned Chebyshev (no reductions) --------
        float rho_prev = 1.f / CH_SIGMA1;
        for (int c = 0; c < NCHEB; c++) {
            kmatvec<4>(kr, i_, seg, act, DS, AP, PART);
            if (t < NR) {
                int ii = t / 4, a = t - ii * 4;
                float v = AP[t] + DS[t];
#pragma unroll
                for (int b = 0; b < 4; b++) v += BSM[ii * 16 + a * 4 + b] * DS[ii * 4 + b];
                XS[t] += DS[t];
                RS[t] -= v;
            }
            __syncthreads();
            float rho = 1.f / (2.f * CH_SIGMA1 - rho_prev);
            if (t < NR) {
                int ii = t / 4, a = t - ii * 4;
                float zz = 0.f;
#pragma unroll
                for (int b = 0; b < 4; b++) zz += MINV[ii * 16 + a * 4 + b] * RS[ii * 4 + b];
                DS[t] = rho * rho_prev * DS[t] + (2.f * rho / CH_DELTA) * zz;
            }
            rho_prev = rho;
            __syncthreads();
        }

        // dz, ds, dlam, dnu, step
        float ds = 0.f, dlam = 0.f, rloc = 3.4e38f;
        if (t < NZ) {
            int ii = t / NW, w = t - ii * NW;
            float zx = 0.f;
#pragma unroll
            for (int a = 0; a < 4; a++) zx += cZ[w][a] * XS[ii * 4 + a];
            float dz = TV[ii] + zx;
            DZ[t] = dz;
            CB[t] = RHS[t] - DDv[t] * dz;
            ds = -R2[t] - dz;
            dlam = (-R3[t] - LAM[t] * ds) / S[t];
            float ra = (ds < 0.f) ? -S[t] / ds : 3.4e38f;
            float rb = (dlam < 0.f) ? -LAM[t] / dlam : 3.4e38f;
            rloc = fminf(ra, rb);
        }
        float alpha = fminf(1.f, 0.99f * blkMin(rloc, SC));
        if (t < NS) {
            float dnu = 0.2f * (CB[t*5] + CB[t*5+1] + CB[t*5+2] + CB[t*5+3] + CB[t*5+4])
                        - KT[t] - TV[t];
            NU[t] += alpha * dnu;
        }
        if (t < NZ) {
            Z[t]   += alpha * DZ[t];
            S[t]   += alpha * ds;
            LAM[t] += alpha * dlam;
        }
        __syncthreads();
    }

    if (t < NZ) g_z[t] = Z[t];
    float sv = 0.f;
    if (t < NS) {
        bool any = false;
#pragma unroll
        for (int w = 0; w < NW; w++) any = any || (Z[t * NW + w] > 0.001f);
        sv = any ? 1.f : 0.f;
    }
    float nsv = blkSum(sv, SC);
    for (int u = NQ * NW + t; u < out_size; u += NT) out[u] = nsv;
}

// ---------- compat GEMM: runs concurrently with k_ipm (separate kernel, own stream-order? No —
// same stream would serialize). So it is a SIBLING grid: launched as part of the same kernel is
// cleanest, but k_ipm needs the support pointer for that. We give the GEMM its own kernel and
// launch it BEFORE k_ipm would serialize it. Instead: fold it into k_ipm via an extra pointer. ----
__global__ void __launch_bounds__(NT, 1)
k_ipm_gemm(const float* __restrict__ sup, const float* __restrict__ query) {
    // grid of 16 CTAs, each computes compat rows for a 128-query tile
    __shared__ float St[32][128];
    __shared__ float Qt[32][128];
    const int t = threadIdx.x;
    const int ty = t >> 5, tx = t & 31;
    const int frow = t >> 3, fc4 = t & 7;
    const int bq0 = blockIdx.x * 128;
    float acc[4][4];
#pragma unroll
    for (int a = 0; a < 4; a++)
#pragma unroll
        for (int b = 0; b < 4; b++) acc[a][b] = 0.f;

    for (int k0 = 0; k0 < DDIM; k0 += 32) {
        float4 svec = make_float4(0.f, 0.f, 0.f, 0.f);
        if (frow < NS) svec = *(const float4*)(sup + (long)frow * DDIM + k0 + 4 * fc4);
        float4 qvec = *(const float4*)(query + (long)(bq0 + frow) * DDIM + k0 + 4 * fc4);
        __syncthreads();
        St[4 * fc4 + 0][frow] = svec.x; St[4 * fc4 + 1][frow] = svec.y;
        St[4 * fc4 + 2][frow] = svec.z; St[4 * fc4 + 3][frow] = svec.w;
        Qt[4 * fc4 + 0][frow] = qvec.x; Qt[4 * fc4 + 1][frow] = qvec.y;
        Qt[4 * fc4 + 2][frow] = qvec.z; Qt[4 * fc4 + 3][frow] = qvec.w;
        __syncthreads();
#pragma unroll
        for (int kk = 0; kk < 32; kk++) {
            float4 a4 = *(float4*)&St[kk][4 * ty];
            float4 b4 = *(float4*)&Qt[kk][4 * tx];
            float av[4] = {a4.x, a4.y, a4.z, a4.w};
            float bv[4] = {b4.x, b4.y, b4.z, b4.w};
#pragma unroll
            for (int mi = 0; mi < 4; mi++)
#pragma unroll
                for (int ni = 0; ni < 4; ni++) acc[mi][ni] += av[mi] * bv[ni];
        }
    }
#pragma unroll
    for (int mi = 0; mi < 4; mi++)
#pragma unroll
        for (int ni = 0; ni < 4; ni++)
            g_compat[(long)(bq0 + 4 * tx + ni) * 128 + 4 * ty + mi] = acc[mi][ni];
}

// ---------------- logits[q][w] = scale * sum_i z[i][w] * compat[q][i] ----------------
__global__ void k_final(const float* __restrict__ scale, float* __restrict__ out) {
    __shared__ float zs[NZ];
    for (int u = threadIdx.x; u < NZ; u += blockDim.x) zs[u] = g_z[u];
    __syncthreads();
    int warp = (blockIdx.x * blockDim.x + threadIdx.x) >> 5;
    int lane = threadIdx.x & 31;
    if (warp >= NQ) return;
    float acc[NW];
#pragma unroll
    for (int w = 0; w < NW; w++) acc[w] = 0.f;
#pragma unroll
    for (int c4 = 0; c4 < 4; c4++) {
        int i = c4 * 32 + lane;
        float cv = (i < NS) ? g_compat[(long)warp * 128 + i] : 0.f;
#pragma unroll
        for (int w = 0; w < NW; w++) acc[w] += zs[i < NS ? i * NW + w : 0] * cv;
    }
#pragma unroll
    for (int w = 0; w < NW; w++)
#pragma unroll
        for (int o = 16; o; o >>= 1) acc[w] += __shfl_down_sync(0xffffffffu, acc[w], o);
    if (lane == 0) {
        float sc = scale[0];
#pragma unroll
        for (int w = 0; w < NW; w++) out[warp * NW + w] = sc * acc[w];
    }
}

extern "C" void kernel_launch(void* const* d_in, const int* in_sizes, int n_in,
                              void* d_out, int out_size) {
    const float* query = nullptr;
    const float* support = nullptr;
    const int* labels = nullptr;
    for (int i = 0; i < n_in; i++) {
        if (in_sizes[i] == NQ * DDIM) query = (const float*)d_in[i];
        else if (in_sizes[i] == NS * DDIM) support = (const float*)d_in[i];
        else if (in_sizes[i] == NS) labels = (const int*)d_in[i];
    }
    const float* scale = (const float*)d_in[n_in - 1];
    float* out = (float*)d_out;

    static int smem_set = 0;
    if (!smem_set) {
        cudaFuncSetAttribute(k_ipm, cudaFuncAttributeMaxDynamicSharedMemorySize, SMEM_BYTES);
        smem_set = 1;
    }

    // NOTE on overlap: k_ipm_gemm (16 CTAs) and k_ipm (1 CTA) are independent until k_final.
    // On one stream they serialize; k_ipm_gemm is launched FIRST so its tail overlaps nothing,
    // but it is short (~70us). The gemmK path feeds k_ipm.
    k_gemmK<<<32, 1024>>>(support);
    k_reduceK<<<16, 1024>>>();
    k_ipm_gemm<<<16, 1024>>>(support, query);
    k_ipm<<<1, NT, SMEM_BYTES>>>(query, labels, out, out_size);
    k_final<<<(NQ * 32 + 255) / 256, 256>>>(scale, out);
}

// round 16
// speedup vs baseline: 4.5365x; 4.5365x over previous
#include <cuda_runtime.h>
#include <cuda_bf16.h>

#define NS    125
#define NW    5
#define NZ    625
#define NR    500
#define DDIM  8192
#define NQ    2048
#define MAXIT 20
#define NCHEB 8
#define NT    512

#define CH_THETA  1.0f
#define CH_DELTA  0.38f
#define CH_SIGMA1 (CH_THETA / CH_DELTA)

__device__ float g_Kslice[8][16384];
__device__ float g_K[16384];
__device__ float g_z[NZ];
__device__ float g_P[NW * DDIM];

// 5x4 orthonormal basis of {v in R^5 : sum v = 0}
__constant__ float cZ[5][4] = {
    { 0.44721360f,  0.44721360f,  0.44721360f,  0.44721360f},
    { 0.63819660f, -0.36180340f, -0.36180340f, -0.36180340f},
    {-0.36180340f,  0.63819660f, -0.36180340f, -0.36180340f},
    {-0.36180340f, -0.36180340f,  0.63819660f, -0.36180340f},
    {-0.36180340f, -0.36180340f, -0.36180340f,  0.63819660f}};

#define FFMA2(d, a, b, c) \
    asm("fma.rn.f32x2 %0, %1, %2, %3;" : "=l"(d) : "l"(a), "l"(b), "l"(c))
#define ADD2(d, a, b) \
    asm("add.rn.f32x2 %0, %1, %2;" : "=l"(d) : "l"(a), "l"(b))

// ---------------- K = S S^T, split-K over 8 slices (deterministic) ----------------
__global__ void k_gemmK(const float* __restrict__ sup) {
    __shared__ float As[16][17], Bs[16][17];
    const int tx = threadIdx.x, ty = threadIdx.y;
    const int bi = blockIdx.y * 16, bj = blockIdx.x * 16;
    const int row = bi + ty;
    float acc = 0.f;
    for (int k0 = blockIdx.z * 1024; k0 < blockIdx.z * 1024 + 1024; k0 += 16) {
        As[ty][tx] = (row < NS) ? sup[(long)row * DDIM + k0 + tx] : 0.f;
        Bs[ty][tx] = (bj + ty < NS) ? sup[(long)(bj + ty) * DDIM + k0 + tx] : 0.f;
        __syncthreads();
#pragma unroll
        for (int k = 0; k < 16; k++) acc += As[ty][k] * Bs[tx][k];
        __syncthreads();
    }
    g_Kslice[blockIdx.z][(bi + ty) * 128 + (bj + tx)] = acc;
}

__global__ void k_reduceK() {
    int idx = blockIdx.x * blockDim.x + threadIdx.x;
    float a = 0.f;
#pragma unroll
    for (int s = 0; s < 8; s++) a += g_Kslice[s][idx];
    g_K[idx] = a;
}

// ---------------- block reductions (512 threads / 16 warps) ----------------
__device__ __forceinline__ float blkSum(float v, float* sc) {
#pragma unroll
    for (int o = 16; o; o >>= 1) v += __shfl_down_sync(0xffffffffu, v, o);
    if ((threadIdx.x & 31) == 0) sc[threadIdx.x >> 5] = v;
    __syncthreads();
    if (threadIdx.x < 32) {
        float x = (threadIdx.x < 16) ? sc[threadIdx.x] : 0.f;
#pragma unroll
        for (int o = 16; o; o >>= 1) x += __shfl_down_sync(0xffffffffu, x, o);
        if (threadIdx.x == 0) sc[32] = x;
    }
    __syncthreads();
    float r = sc[32];
    __syncthreads();
    return r;
}

__device__ __forceinline__ float blkMin(float v, float* sc) {
#pragma unroll
    for (int o = 16; o; o >>= 1) v = fminf(v, __shfl_down_sync(0xffffffffu, v, o));
    if ((threadIdx.x & 31) == 0) sc[threadIdx.x >> 5] = v;
    __syncthreads();
    if (threadIdx.x < 32) {
        float x = (threadIdx.x < 16) ? sc[threadIdx.x] : 3.4e38f;
#pragma unroll
        for (int o = 16; o; o >>= 1) x = fminf(x, __shfl_down_sync(0xffffffffu, x, o));
        if (threadIdx.x == 0) sc[32] = x;
    }
    __syncthreads();
    float r = sc[32];
    __syncthreads();
    return r;
}

// smem float offsets
#define O_Z     0
#define O_S     640
#define O_LAM   1268
#define O_DD    1896
#define O_R2    2524
#define O_R3    3152
#define O_RHS   3780
#define O_CB    4408
#define O_DZ    5036
#define O_TV    5676
#define O_KT    5804
#define O_KD    5932
#define O_NU    6060
#define O_XS    6188
#define O_RS    6700
#define O_DS    7212
#define O_MINV  7724
#define O_BSM   9724
#define O_PART  11724
#define O_SC    14284
#define O_LB    14348
#define SMEM_FLOATS 14476
#define SMEM_BYTES  (SMEM_FLOATS * 4)

__global__ void __launch_bounds__(NT, 1)
k_ipm(const int* __restrict__ lblg, float* __restrict__ out, int out_size) {
    extern __shared__ float sm[];
    float* Z = sm + O_Z;     float* S = sm + O_S;     float* LAM = sm + O_LAM;
    float* DDv = sm + O_DD;  float* R2 = sm + O_R2;   float* R3 = sm + O_R3;
    float* RHS = sm + O_RHS; float* CB = sm + O_CB;   float* DZ = sm + O_DZ;
    float* TV = sm + O_TV;   float* KT = sm + O_KT;   float* KD = sm + O_KD;
    float* NU = sm + O_NU;   float* XS = sm + O_XS;   float* RS = sm + O_RS;
    float* DS = sm + O_DS;
    float* MINV = sm + O_MINV; float* BSM = sm + O_BSM; float* PART = sm + O_PART;
    float* SC = sm + O_SC;   int* LB = (int*)(sm + O_LB);
    unsigned long long* P64 = (unsigned long long*)PART;

    const int t = threadIdx.x;
    const int i_ = t % NS, seg = t / NS;       // seg in 0..3 for t<500
    const bool act = (t < 500);

    // register-resident K row slice, duplicated-pair packed: K[i_][seg*32 .. +31]
    unsigned long long krp[32];
    if (act) {
#pragma unroll
        for (int k = 0; k < 32; k++) {
            float kv = g_K[i_ * 128 + seg * 32 + k];
            asm("mov.b64 %0, {%1, %1};" : "=l"(krp[k]) : "f"(kv));
        }
    } else {
#pragma unroll
        for (int k = 0; k < 32; k++) krp[k] = 0ull;
    }

    for (int u = t; u < 640; u += NT) { Z[u] = 0.f; DZ[u] = 0.f; }
    for (int u = t; u < NZ; u += NT) { S[u] = 1.f; LAM[u] = 1.f; }
    if (t < 128) { NU[t] = 0.f; TV[t] = 0.f; KT[t] = 0.f; }
    DS[t] = 0.f;                                   // full 512, padding zeroed
    if (t < NS) { KD[t] = g_K[t * 128 + t]; LB[t] = lblg[t]; }
    __syncthreads();

    for (int it = 0; it < MAXIT; it++) {
        // ---- KZ (5 cols): scalar matvec, K unpacked from krp ----
        if (act) {
            float a0 = 0.f, a1 = 0.f, a2 = 0.f, a3 = 0.f, a4 = 0.f;
            const float* Vb = Z + seg * 32 * 5;
#pragma unroll
            for (int k = 0; k < 32; k++) {
                float kv, hi_;
                asm("mov.b64 {%0, %1}, %2;" : "=f"(kv), "=f"(hi_) : "l"(krp[k]));
                a0 += kv * Vb[k * 5 + 0];
                a1 += kv * Vb[k * 5 + 1];
                a2 += kv * Vb[k * 5 + 2];
                a3 += kv * Vb[k * 5 + 3];
                a4 += kv * Vb[k * 5 + 4];
            }
            PART[(0 * 4 + seg) * 128 + i_] = a0;
            PART[(1 * 4 + seg) * 128 + i_] = a1;
            PART[(2 * 4 + seg) * 128 + i_] = a2;
            PART[(3 * 4 + seg) * 128 + i_] = a3;
            PART[(4 * 4 + seg) * 128 + i_] = a4;
        }
        __syncthreads();
        for (int u = t; u < NZ; u += NT) {
            int c = u / NS, ii = u - c * NS;
            float s = 0.f;
#pragma unroll
            for (int g = 0; g < 4; g++) s += PART[(c * 4 + g) * 128 + ii];
            DZ[ii * NW + c] = s;
        }
        __syncthreads();

        // ---- mu ----
        float ml = 0.f;
        for (int u = t; u < NZ; u += NT) ml += S[u] * LAM[u];
        float mu = 0.1f * blkSum(ml, SC) * (1.f / 625.f);

        // ---- residuals ----
        for (int u = t; u < NZ; u += NT) {
            int ii = u / NW, w = u - ii * NW;
            float e = (LB[ii] == w) ? -1.f : 0.f;
            float h = (LB[ii] == w) ? 0.1f : 0.f;
            float sv = S[u], lv = LAM[u], zv = Z[u];
            float r1 = (DZ[u] + zv) + e + lv + NU[ii];
            float r2v = zv + sv - h;
            float r3v = lv * sv - mu;
            R2[u] = r2v; R3[u] = r3v; DDv[u] = lv / sv;
            RHS[u] = -(r1 + (lv * r2v - r3v) / sv);
        }
        if (t < NS) {
            TV[t] = -0.2f * (Z[t*5] + Z[t*5+1] + Z[t*5+2] + Z[t*5+3] + Z[t*5+4]);
            KT[t] = -0.2f * (DZ[t*5] + DZ[t*5+1] + DZ[t*5+2] + DZ[t*5+3] + DZ[t*5+4]);
        }
        __syncthreads();

        // ---- c = rhs1 - H dz_p ; per-sample 4x4 preconditioner ----
        for (int u = t; u < NZ; u += NT) {
            int ii = u / NW;
            CB[u] = RHS[u] - KT[ii] - TV[ii] * (1.f + DDv[u]);
        }
        if (t < NS) {
            float dd[5];
#pragma unroll
            for (int w = 0; w < NW; w++) dd[w] = DDv[t * NW + w];
            float M[4][4], Inv[4][4];
#pragma unroll
            for (int a = 0; a < 4; a++)
#pragma unroll
                for (int b = 0; b < 4; b++) {
                    float s2 = 0.f;
#pragma unroll
                    for (int w = 0; w < NW; w++) s2 += cZ[w][a] * dd[w] * cZ[w][b];
                    BSM[t * 16 + a * 4 + b] = s2;
                    M[a][b] = s2;
                    Inv[a][b] = (a == b) ? 1.f : 0.f;
                }
            float dg = KD[t] + 1.f;
#pragma unroll
            for (int a = 0; a < 4; a++) M[a][a] += dg;
#pragma unroll
            for (int k = 0; k < 4; k++) {
                float piv = 1.f / M[k][k];
#pragma unroll
                for (int c = 0; c < 4; c++) { M[k][c] *= piv; Inv[k][c] *= piv; }
#pragma unroll
                for (int r = 0; r < 4; r++) if (r != k) {
                    float f = M[r][k];
#pragma unroll
                    for (int c = 0; c < 4; c++) { M[r][c] -= f * M[k][c]; Inv[r][c] -= f * Inv[k][c]; }
                }
            }
#pragma unroll
            for (int a = 0; a < 4; a++)
#pragma unroll
                for (int b = 0; b < 4; b++) MINV[t * 16 + a * 4 + b] = Inv[a][b];
        }
        __syncthreads();

        // ---- reduced rhs + Chebyshev init ----
        if (t < NR) {
            int ii = t >> 2, a = t & 3;
            float bv = 0.f;
#pragma unroll
            for (int w = 0; w < NW; w++) bv += cZ[w][a] * CB[ii * NW + w];
            RS[t] = bv; XS[t] = 0.f;
        }
        __syncthreads();
        if (t < NR) {
            int ii = t >> 2, a = t & 3;
            float zz = 0.f;
#pragma unroll
            for (int b = 0; b < 4; b++) zz += MINV[ii * 16 + a * 4 + b] * RS[ii * 4 + b];
            DS[t] = zz;
        }
        __syncthreads();

        // ---- preconditioned Chebyshev (no inner products) ----
        float rho_prev = 1.f / CH_SIGMA1;
        for (int c = 0; c < NCHEB; c++) {
            // A: packed K matvec on DS
            if (act) {
                unsigned long long a0 = 0ull, a1 = 0ull;
                const ulonglong2* v2 = (const ulonglong2*)DS + seg * 32;
#pragma unroll
                for (int k = 0; k < 32; k++) {
                    ulonglong2 v = v2[k];
                    FFMA2(a0, krp[k], v.x, a0);
                    FFMA2(a1, krp[k], v.y, a1);
                }
                P64[(0 * 4 + seg) * 128 + i_] = a0;
                P64[(1 * 4 + seg) * 128 + i_] = a1;
            }
            __syncthreads();
            // B: consume partials, apply full reduced operator, update x,r
            if (t < NR) {
                int ii = t >> 2, a = t & 3, p = a >> 1;
                unsigned long long s0 = P64[(p * 4 + 0) * 128 + ii];
                ADD2(s0, s0, P64[(p * 4 + 1) * 128 + ii]);
                ADD2(s0, s0, P64[(p * 4 + 2) * 128 + ii]);
                ADD2(s0, s0, P64[(p * 4 + 3) * 128 + ii]);
                float lo, hi;
                asm("mov.b64 {%0, %1}, %2;" : "=f"(lo), "=f"(hi) : "l"(s0));
                float ap = (a & 1) ? hi : lo;
                float dsv = DS[t];
                float v = ap + dsv;
#pragma unroll
                for (int b = 0; b < 4; b++) v += BSM[ii * 16 + a * 4 + b] * DS[ii * 4 + b];
                XS[t] += dsv;
                RS[t] -= v;
            }
            __syncthreads();
            // C: next direction
            float rho = 1.f / (2.f * CH_SIGMA1 - rho_prev);
            if (t < NR) {
                int ii = t >> 2, a = t & 3;
                float zz = 0.f;
#pragma unroll
                for (int b = 0; b < 4; b++) zz += MINV[ii * 16 + a * 4 + b] * RS[ii * 4 + b];
                DS[t] = rho * rho_prev * DS[t] + (2.f * rho / CH_DELTA) * zz;
            }
            rho_prev = rho;
            __syncthreads();
        }

        // ---- dz, step length ----
        float rloc = 3.4e38f;
        for (int u = t; u < NZ; u += NT) {
            int ii = u / NW, w = u - ii * NW;
            float zx = 0.f;
#pragma unroll
            for (int a = 0; a < 4; a++) zx += cZ[w][a] * XS[ii * 4 + a];
            float dz = TV[ii] + zx;
            DZ[u] = dz;
            CB[u] = RHS[u] - DDv[u] * dz;
            float ds = -R2[u] - dz;
            float dlam = (-R3[u] - LAM[u] * ds) / S[u];
            rloc = fminf(rloc, (ds < 0.f) ? -S[u] / ds : 3.4e38f);
            rloc = fminf(rloc, (dlam < 0.f) ? -LAM[u] / dlam : 3.4e38f);
        }
        float alpha = fminf(1.f, 0.99f * blkMin(rloc, SC));
        if (t < NS) {
            float dnu = 0.2f * (CB[t*5] + CB[t*5+1] + CB[t*5+2] + CB[t*5+3] + CB[t*5+4])
                        - KT[t] - TV[t];
            NU[t] += alpha * dnu;
        }
        for (int u = t; u < NZ; u += NT) {
            float dz = DZ[u];
            float ds = -R2[u] - dz;
            float dlam = (-R3[u] - LAM[u] * ds) / S[u];
            Z[u]   += alpha * dz;
            S[u]   += alpha * ds;
            LAM[u] += alpha * dlam;
        }
        __syncthreads();
    }

    for (int u = t; u < NZ; u += NT) g_z[u] = Z[u];
    float sv = 0.f;
    if (t < NS) {
        bool any = false;
#pragma unroll
        for (int w = 0; w < NW; w++) any = any || (Z[t * NW + w] > 0.001f);
        sv = any ? 1.f : 0.f;
    }
    float nsv = blkSum(sv, SC);
    for (int u = NQ * NW + t; u < out_size; u += NT) out[u] = nsv;
}

// ---------------- P[w][d] = sum_i z[i,w] * sup[i][d] ----------------
__global__ void k_proj(const float* __restrict__ sup) {
    __shared__ float zs[NZ];
    for (int u = threadIdx.x; u < NZ; u += blockDim.x) zs[u] = g_z[u];
    __syncthreads();
    int d = blockIdx.x * blockDim.x + threadIdx.x;
    float acc[NW];
#pragma unroll
    for (int w = 0; w < NW; w++) acc[w] = 0.f;
    for (int i = 0; i < NS; i++) {
        float f = sup[(long)i * DDIM + d];
#pragma unroll
        for (int w = 0; w < NW; w++) acc[w] += zs[i * NW + w] * f;
    }
#pragma unroll
    for (int w = 0; w < NW; w++) g_P[w * DDIM + d] = acc[w];
}

// ---------------- logits[q][w] = scale * dot(Q[q], P[w]) ----------------
__global__ void k_logits(const float* __restrict__ query, const float* __restrict__ scale,
                         float* __restrict__ out) {
    int warp = (blockIdx.x * blockDim.x + threadIdx.x) >> 5;
    int lane = threadIdx.x & 31;
    if (warp >= NQ) return;
    const float4* q4 = (const float4*)(query + (long)warp * DDIM);
    const float4* p4 = (const float4*)g_P;
    float acc[NW];
#pragma unroll
    for (int w = 0; w < NW; w++) acc[w] = 0.f;
    for (int j = lane; j < DDIM / 4; j += 32) {
        float4 q = q4[j];
#pragma unroll
        for (int w = 0; w < NW; w++) {
            float4 p = p4[w * (DDIM / 4) + j];
            acc[w] += q.x * p.x + q.y * p.y + q.z * p.z + q.w * p.w;
        }
    }
#pragma unroll
    for (int w = 0; w < NW; w++) {
#pragma unroll
        for (int o = 16; o; o >>= 1) acc[w] += __shfl_down_sync(0xffffffffu, acc[w], o);
    }
    if (lane == 0) {
        float sc = scale[0];
#pragma unroll
        for (int w = 0; w < NW; w++) out[warp * NW + w] = sc * acc[w];
    }
}

extern "C" void kernel_launch(void* const* d_in, const int* in_sizes, int n_in,
                              void* d_out, int out_size) {
    const float* query = nullptr;
    const float* support = nullptr;
    const int* labels = nullptr;
    for (int i = 0; i < n_in; i++) {
        if (in_sizes[i] == NQ * DDIM) query = (const float*)d_in[i];
        else if (in_sizes[i] == NS * DDIM) support = (const float*)d_in[i];
        else if (in_sizes[i] == NS) labels = (const int*)d_in[i];
    }
    const float* scale = (const float*)d_in[n_in - 1];
    float* out = (float*)d_out;

    static int smem_set = 0;
    if (!smem_set) {
        cudaFuncSetAttribute(k_ipm, cudaFuncAttributeMaxDynamicSharedMemorySize, SMEM_BYTES);
        smem_set = 1;
    }

    k_gemmK<<<dim3(8, 8, 8), dim3(16, 16)>>>(support);
    k_reduceK<<<16, 1024>>>();
    k_ipm<<<1, NT, SMEM_BYTES>>>(labels, out, out_size);
    k_proj<<<DDIM / 1024, 1024>>>(support);
    k_logits<<<(NQ * 32 + 255) / 256, 256>>>(query, scale, out);
}

// round 17
// speedup vs baseline: 5.0892x; 1.1218x over previous
#include <cuda_runtime.h>
#include <cuda_bf16.h>

#define NS    125
#define NW    5
#define NZ    625
#define NR    500
#define DDIM  8192
#define NQ    2048
#define MAXIT 20
#define NCHEB 6
#define NT    512

#define CH_THETA  1.0f
#define CH_DELTA  0.38f
#define CH_SIGMA1 (CH_THETA / CH_DELTA)

__device__ float g_Kslice[32][16384];
__device__ float g_K[16384];
__device__ float g_z[NZ];
__device__ float g_P[NW * DDIM];

// 5x4 orthonormal basis of {v in R^5 : sum v = 0}
__constant__ float cZ[5][4] = {
    { 0.44721360f,  0.44721360f,  0.44721360f,  0.44721360f},
    { 0.63819660f, -0.36180340f, -0.36180340f, -0.36180340f},
    {-0.36180340f,  0.63819660f, -0.36180340f, -0.36180340f},
    {-0.36180340f, -0.36180340f,  0.63819660f, -0.36180340f},
    {-0.36180340f, -0.36180340f, -0.36180340f,  0.63819660f}};

#define FFMA2(d, a, b, c) \
    asm("fma.rn.f32x2 %0, %1, %2, %3;" : "=l"(d) : "l"(a), "l"(b), "l"(c))
#define ADD2(d, a, b) \
    asm("add.rn.f32x2 %0, %1, %2;" : "=l"(d) : "l"(a), "l"(b))

// ======== K = S S^T : 32 k-slices (256 k each), one 128x128 tile per CTA ========
__global__ void __launch_bounds__(1024, 1) k_gemmK(const float* __restrict__ sup) {
    __shared__ float St[32][128];
    const int t = threadIdx.x;
    const int ty = t >> 5, tx = t & 31;
    const int frow = t >> 3, fc4 = t & 7;
    float acc[4][4];
#pragma unroll
    for (int a = 0; a < 4; a++)
#pragma unroll
        for (int b = 0; b < 4; b++) acc[a][b] = 0.f;

    const int kbase = blockIdx.x * 256;
    for (int k0 = kbase; k0 < kbase + 256; k0 += 32) {
        float4 sv = make_float4(0.f, 0.f, 0.f, 0.f);
        if (frow < NS) sv = *(const float4*)(sup + (long)frow * DDIM + k0 + 4 * fc4);
        __syncthreads();
        St[4 * fc4 + 0][frow] = sv.x;
        St[4 * fc4 + 1][frow] = sv.y;
        St[4 * fc4 + 2][frow] = sv.z;
        St[4 * fc4 + 3][frow] = sv.w;
        __syncthreads();
#pragma unroll
        for (int kk = 0; kk < 32; kk++) {
            float4 a4 = *(float4*)&St[kk][4 * ty];
            float4 b4 = *(float4*)&St[kk][4 * tx];
            float av[4] = {a4.x, a4.y, a4.z, a4.w};
            float bv[4] = {b4.x, b4.y, b4.z, b4.w};
#pragma unroll
            for (int mi = 0; mi < 4; mi++)
#pragma unroll
                for (int ni = 0; ni < 4; ni++) acc[mi][ni] += av[mi] * bv[ni];
        }
    }
#pragma unroll
    for (int mi = 0; mi < 4; mi++)
#pragma unroll
        for (int ni = 0; ni < 4; ni++)
            g_Kslice[blockIdx.x][(4 * ty + mi) * 128 + 4 * tx + ni] = acc[mi][ni];
}

__global__ void k_reduceK() {
    int idx = blockIdx.x * blockDim.x + threadIdx.x;
    float a = 0.f;
#pragma unroll
    for (int s = 0; s < 32; s++) a += g_Kslice[s][idx];
    g_K[idx] = a;
}

// ---------------- block reductions (512 threads / 16 warps) ----------------
__device__ __forceinline__ float blkSum(float v, float* sc) {
#pragma unroll
    for (int o = 16; o; o >>= 1) v += __shfl_down_sync(0xffffffffu, v, o);
    if ((threadIdx.x & 31) == 0) sc[threadIdx.x >> 5] = v;
    __syncthreads();
    if (threadIdx.x < 32) {
        float x = (threadIdx.x < 16) ? sc[threadIdx.x] : 0.f;
#pragma unroll
        for (int o = 16; o; o >>= 1) x += __shfl_down_sync(0xffffffffu, x, o);
        if (threadIdx.x == 0) sc[32] = x;
    }
    __syncthreads();
    float r = sc[32];
    __syncthreads();
    return r;
}

__device__ __forceinline__ float blkMin(float v, float* sc) {
#pragma unroll
    for (int o = 16; o; o >>= 1) v = fminf(v, __shfl_down_sync(0xffffffffu, v, o));
    if ((threadIdx.x & 31) == 0) sc[threadIdx.x >> 5] = v;
    __syncthreads();
    if (threadIdx.x < 32) {
        float x = (threadIdx.x < 16) ? sc[threadIdx.x] : 3.4e38f;
#pragma unroll
        for (int o = 16; o; o >>= 1) x = fminf(x, __shfl_down_sync(0xffffffffu, x, o));
        if (threadIdx.x == 0) sc[32] = x;
    }
    __syncthreads();
    float r = sc[32];
    __syncthreads();
    return r;
}

// smem float offsets (generous padding; garbage-lane reads stay in-bounds)
#define O_Z     0
#define O_S     640
#define O_LAM   1280
#define O_DD    1920
#define O_R2    2560
#define O_R3    3200
#define O_RHS   3840
#define O_CB    4480
#define O_DZ    5120
#define O_TV    5760
#define O_KT    5888
#define O_KD    6016
#define O_NU    6144
#define O_XS    6272
#define O_DS    6784
#define O_MINV  7296
#define O_BSM   9344
#define O_ZPP   11392
#define O_Z4    11904
#define O_PART  12032
#define O_SC    14592
#define O_LB    14656
#define SMEM_FLOATS 14784
#define SMEM_BYTES  (SMEM_FLOATS * 4)

__global__ void __launch_bounds__(NT, 1)
k_ipm(const int* __restrict__ lblg, float* __restrict__ out, int out_size) {
    extern __shared__ float sm[];
    float* Z = sm + O_Z;     float* S = sm + O_S;     float* LAM = sm + O_LAM;
    float* DDv = sm + O_DD;  float* R2 = sm + O_R2;   float* R3 = sm + O_R3;
    float* RHS = sm + O_RHS; float* CB = sm + O_CB;   float* DZ = sm + O_DZ;
    float* TV = sm + O_TV;   float* KT = sm + O_KT;   float* KD = sm + O_KD;
    float* NU = sm + O_NU;   float* XS = sm + O_XS;   float* DS = sm + O_DS;
    float* MINV = sm + O_MINV; float* BSM = sm + O_BSM;
    float* Z4 = sm + O_Z4;   float* PART = sm + O_PART;
    float* SC = sm + O_SC;   int* LB = (int*)(sm + O_LB);
    ulonglong2* ZPP = (ulonglong2*)(sm + O_ZPP);
    unsigned long long* P64 = (unsigned long long*)PART;

    const int t = threadIdx.x;
    const int i_ = t % NS, seg = t / NS;     // seg 0..3 for t<500
    const bool act = (t < 500);
    const int ii4 = t >> 2, aa = t & 3;      // reduced-system quad coords

    // register-resident packed K row slice: K[i_][seg*32 .. +31], duplicated pairs
    unsigned long long krp[32];
    if (act) {
#pragma unroll
        for (int k = 0; k < 32; k++) {
            float kv = g_K[i_ * 128 + seg * 32 + k];
            asm("mov.b64 %0, {%1, %1};" : "=l"(krp[k]) : "f"(kv));
        }
    } else {
#pragma unroll
        for (int k = 0; k < 32; k++) krp[k] = 0ull;
    }

    for (int u = t; u < 640; u += NT) Z[u] = 0.f;
    for (int u = t; u < NZ; u += NT) { S[u] = 1.f; LAM[u] = 1.f; }
    if (t < 128) {
        NU[t] = 0.f; TV[t] = 0.f; KT[t] = 0.f;
        ZPP[t] = make_ulonglong2(0ull, 0ull); Z4[t] = 0.f;
    }
    DS[t] = 0.f;
    if (t < NS) { KD[t] = g_K[t * 128 + t]; LB[t] = lblg[t]; }
    __syncthreads();

    for (int it = 0; it < MAXIT; it++) {
        // ---- A: packed KZ matvec (5 cols as 2 pairs + 1 scalar) ----
        if (act) {
            unsigned long long a01 = 0ull, a23 = 0ull;
            float a4 = 0.f;
#pragma unroll
            for (int k = 0; k < 32; k++) {
                int j = seg * 32 + k;
                ulonglong2 zp = ZPP[j];
                float kv, hi_;
                asm("mov.b64 {%0, %1}, %2;" : "=f"(kv), "=f"(hi_) : "l"(krp[k]));
                FFMA2(a01, krp[k], zp.x, a01);
                FFMA2(a23, krp[k], zp.y, a23);
                a4 += kv * Z4[j];
            }
            P64[(0 * 4 + seg) * 128 + i_] = a01;
            P64[(1 * 4 + seg) * 128 + i_] = a23;
            PART[2048 + seg * 128 + i_] = a4;
        }
        __syncthreads();
        // consumer -> DZ (Kz)
        for (int u = t; u < NZ; u += NT) {
            int ii = u / NW, w = u - ii * NW;
            float s;
            if (w < 4) {
                int p = w >> 1;
                unsigned long long s0 = P64[(p * 4 + 0) * 128 + ii];
                ADD2(s0, s0, P64[(p * 4 + 1) * 128 + ii]);
                ADD2(s0, s0, P64[(p * 4 + 2) * 128 + ii]);
                ADD2(s0, s0, P64[(p * 4 + 3) * 128 + ii]);
                float lo, hi;
                asm("mov.b64 {%0, %1}, %2;" : "=f"(lo), "=f"(hi) : "l"(s0));
                s = (w & 1) ? hi : lo;
            } else {
                s = PART[2048 + 0 * 128 + ii] + PART[2048 + 1 * 128 + ii]
                  + PART[2048 + 2 * 128 + ii] + PART[2048 + 3 * 128 + ii];
            }
            DZ[u] = s;
        }

        // ---- mu (blkSum's internal barriers also order DZ writes) ----
        float ml = 0.f;
        for (int u = t; u < NZ; u += NT) ml += S[u] * LAM[u];
        float mu = 0.1f * blkSum(ml, SC) * (1.f / 625.f);

        // ---- residuals ----
        for (int u = t; u < NZ; u += NT) {
            int ii = u / NW, w = u - ii * NW;
            float e = (LB[ii] == w) ? -1.f : 0.f;
            float h = (LB[ii] == w) ? 0.1f : 0.f;
            float sv = S[u], lv = LAM[u], zv = Z[u];
            float r1 = (DZ[u] + zv) + e + lv + NU[ii];
            float r2v = zv + sv - h;
            float r3v = lv * sv - mu;
            R2[u] = r2v; R3[u] = r3v; DDv[u] = lv / sv;
            RHS[u] = -(r1 + (lv * r2v - r3v) / sv);
        }
        if (t < NS) {
            TV[t] = -0.2f * (Z[t*5] + Z[t*5+1] + Z[t*5+2] + Z[t*5+3] + Z[t*5+4]);
            KT[t] = -0.2f * (DZ[t*5] + DZ[t*5+1] + DZ[t*5+2] + DZ[t*5+3] + DZ[t*5+4]);
        }
        __syncthreads();

        // ---- c = rhs1 - H dz_p ; per-sample 4x4 preconditioner ----
        for (int u = t; u < NZ; u += NT) {
            int ii = u / NW;
            CB[u] = RHS[u] - KT[ii] - TV[ii] * (1.f + DDv[u]);
        }
        if (t < NS) {
            float dd[5];
#pragma unroll
            for (int w = 0; w < NW; w++) dd[w] = DDv[t * NW + w];
            float M[4][4], Inv[4][4];
#pragma unroll
            for (int a = 0; a < 4; a++)
#pragma unroll
                for (int b = 0; b < 4; b++) {
                    float s2 = 0.f;
#pragma unroll
                    for (int w = 0; w < NW; w++) s2 += cZ[w][a] * dd[w] * cZ[w][b];
                    BSM[t * 16 + a * 4 + b] = s2;
                    M[a][b] = s2;
                    Inv[a][b] = (a == b) ? 1.f : 0.f;
                }
            float dg = KD[t] + 1.f;
#pragma unroll
            for (int a = 0; a < 4; a++) M[a][a] += dg;
#pragma unroll
            for (int k = 0; k < 4; k++) {
                float piv = 1.f / M[k][k];
#pragma unroll
                for (int c = 0; c < 4; c++) { M[k][c] *= piv; Inv[k][c] *= piv; }
#pragma unroll
                for (int r = 0; r < 4; r++) if (r != k) {
                    float f = M[r][k];
#pragma unroll
                    for (int c = 0; c < 4; c++) { M[r][c] -= f * M[k][c]; Inv[r][c] -= f * Inv[k][c]; }
                }
            }
#pragma unroll
            for (int a = 0; a < 4; a++)
#pragma unroll
                for (int b = 0; b < 4; b++) MINV[t * 16 + a * 4 + b] = Inv[a][b];
        }
        __syncthreads();

        // ---- Chebyshev init: rs/xs/ds in registers, quad exchange via shuffles ----
        float rs, xs = 0.f, ds;
        {
            float bv = 0.f;
#pragma unroll
            for (int w = 0; w < NW; w++) bv += cZ[w][aa] * CB[ii4 * NW + w];
            rs = bv;
            float q1 = __shfl_xor_sync(0xffffffffu, rs, 1);
            float q2 = __shfl_xor_sync(0xffffffffu, rs, 2);
            float q3 = __shfl_xor_sync(0xffffffffu, rs, 3);
            const float* Mi = MINV + ii4 * 16 + aa * 4;
            ds = Mi[aa] * rs + Mi[aa ^ 1] * q1 + Mi[aa ^ 2] * q2 + Mi[aa ^ 3] * q3;
        }
        DS[t] = (t < NR) ? ds : 0.f;
        __syncthreads();

        float rho_prev = 1.f / CH_SIGMA1;
        for (int c = 0; c < NCHEB; c++) {
            // matvec on DS (packed)
            if (act) {
                unsigned long long a0 = 0ull, a1 = 0ull;
                const ulonglong2* v2 = (const ulonglong2*)DS + seg * 32;
#pragma unroll
                for (int k = 0; k < 32; k++) {
                    ulonglong2 v = v2[k];
                    FFMA2(a0, krp[k], v.x, a0);
                    FFMA2(a1, krp[k], v.y, a1);
                }
                P64[(0 * 4 + seg) * 128 + i_] = a0;
                P64[(1 * 4 + seg) * 128 + i_] = a1;
            }
            __syncthreads();
            float rho = 1.f / (2.f * CH_SIGMA1 - rho_prev);
            {
                int p = aa >> 1;
                unsigned long long s0 = P64[(p * 4 + 0) * 128 + ii4];
                ADD2(s0, s0, P64[(p * 4 + 1) * 128 + ii4]);
                ADD2(s0, s0, P64[(p * 4 + 2) * 128 + ii4]);
                ADD2(s0, s0, P64[(p * 4 + 3) * 128 + ii4]);
                float lo, hi;
                asm("mov.b64 {%0, %1}, %2;" : "=f"(lo), "=f"(hi) : "l"(s0));
                float ap = (aa & 1) ? hi : lo;
                float d1 = __shfl_xor_sync(0xffffffffu, ds, 1);
                float d2 = __shfl_xor_sync(0xffffffffu, ds, 2);
                float d3 = __shfl_xor_sync(0xffffffffu, ds, 3);
                const float* Bi = BSM + ii4 * 16 + aa * 4;
                float v = ap + ds + Bi[aa] * ds + Bi[aa ^ 1] * d1
                        + Bi[aa ^ 2] * d2 + Bi[aa ^ 3] * d3;
                xs += ds;
                rs -= v;
                float q1 = __shfl_xor_sync(0xffffffffu, rs, 1);
                float q2 = __shfl_xor_sync(0xffffffffu, rs, 2);
                float q3 = __shfl_xor_sync(0xffffffffu, rs, 3);
                const float* Mi = MINV + ii4 * 16 + aa * 4;
                float zz = Mi[aa] * rs + Mi[aa ^ 1] * q1 + Mi[aa ^ 2] * q2 + Mi[aa ^ 3] * q3;
                ds = rho * rho_prev * ds + (2.f * rho / CH_DELTA) * zz;
                DS[t] = (t < NR) ? ds : 0.f;
            }
            rho_prev = rho;
            __syncthreads();
        }
        if (t < NR) XS[t] = xs;
        __syncthreads();

        // ---- dz, step length ----
        float rloc = 3.4e38f;
        for (int u = t; u < NZ; u += NT) {
            int ii = u / NW, w = u - ii * NW;
            float zx = 0.f;
#pragma unroll
            for (int a = 0; a < 4; a++) zx += cZ[w][a] * XS[ii * 4 + a];
            float dz = TV[ii] + zx;
            DZ[u] = dz;
            CB[u] = RHS[u] - DDv[u] * dz;
            float dsv = -R2[u] - dz;
            float dlam = (-R3[u] - LAM[u] * dsv) / S[u];
            rloc = fminf(rloc, (dsv < 0.f) ? -S[u] / dsv : 3.4e38f);
            rloc = fminf(rloc, (dlam < 0.f) ? -LAM[u] / dlam : 3.4e38f);
        }
        float alpha = fminf(1.f, 0.99f * blkMin(rloc, SC));
        if (t < NS) {
            float dnu = 0.2f * (CB[t*5] + CB[t*5+1] + CB[t*5+2] + CB[t*5+3] + CB[t*5+4])
                        - KT[t] - TV[t];
            NU[t] += alpha * dnu;
        }
        for (int u = t; u < NZ; u += NT) {
            float dz = DZ[u];
            float dsv = -R2[u] - dz;
            float dlam = (-R3[u] - LAM[u] * dsv) / S[u];
            Z[u]   += alpha * dz;
            S[u]   += alpha * dsv;
            LAM[u] += alpha * dlam;
        }
        __syncthreads();
        // repack Z for next A-phase
        if (t < 128) {
            float z0 = 0.f, z1 = 0.f, z2 = 0.f, z3 = 0.f, z4 = 0.f;
            if (t < NS) {
                z0 = Z[t*5]; z1 = Z[t*5+1]; z2 = Z[t*5+2]; z3 = Z[t*5+3]; z4 = Z[t*5+4];
            }
            unsigned long long p01, p23;
            asm("mov.b64 %0, {%1, %2};" : "=l"(p01) : "f"(z0), "f"(z1));
            asm("mov.b64 %0, {%1, %2};" : "=l"(p23) : "f"(z2), "f"(z3));
            ZPP[t] = make_ulonglong2(p01, p23);
            Z4[t] = z4;
        }
        __syncthreads();
    }

    for (int u = t; u < NZ; u += NT) g_z[u] = Z[u];
    float sv = 0.f;
    if (t < NS) {
        bool any = false;
#pragma unroll
        for (int w = 0; w < NW; w++) any = any || (Z[t * NW + w] > 0.001f);
        sv = any ? 1.f : 0.f;
    }
    float nsv = blkSum(sv, SC);
    for (int u = NQ * NW + t; u < out_size; u += NT) out[u] = nsv;
}

// ---------------- P[w][d] = sum_i z[i,w] * sup[i][d]  (32 CTAs x 256) ----------------
__global__ void k_proj(const float* __restrict__ sup) {
    __shared__ float zs[NZ];
    for (int u = threadIdx.x; u < NZ; u += blockDim.x) zs[u] = g_z[u];
    __syncthreads();
    int d = blockIdx.x * blockDim.x + threadIdx.x;
    float acc[NW];
#pragma unroll
    for (int w = 0; w < NW; w++) acc[w] = 0.f;
#pragma unroll 5
    for (int i = 0; i < NS; i++) {
        float f = sup[(long)i * DDIM + d];
#pragma unroll
        for (int w = 0; w < NW; w++) acc[w] += zs[i * NW + w] * f;
    }
#pragma unroll
    for (int w = 0; w < NW; w++) g_P[w * DDIM + d] = acc[w];
}

// ---------------- logits[q][w] = scale * dot(Q[q], P[w]) ----------------
__global__ void k_logits(const float* __restrict__ query, const float* __restrict__ scale,
                         float* __restrict__ out) {
    int warp = (blockIdx.x * blockDim.x + threadIdx.x) >> 5;
    int lane = threadIdx.x & 31;
    if (warp >= NQ) return;
    const float4* q4 = (const float4*)(query + (long)warp * DDIM);
    const float4* p4 = (const float4*)g_P;
    float acc[NW];
#pragma unroll
    for (int w = 0; w < NW; w++) acc[w] = 0.f;
#pragma unroll 4
    for (int j = lane; j < DDIM / 4; j += 32) {
        float4 q = q4[j];
#pragma unroll
        for (int w = 0; w < NW; w++) {
            float4 p = p4[w * (DDIM / 4) + j];
            acc[w] += q.x * p.x + q.y * p.y + q.z * p.z + q.w * p.w;
        }
    }
#pragma unroll
    for (int w = 0; w < NW; w++) {
#pragma unroll
        for (int o = 16; o; o >>= 1) acc[w] += __shfl_down_sync(0xffffffffu, acc[w], o);
    }
    if (lane == 0) {
        float sc = scale[0];
#pragma unroll
        for (int w = 0; w < NW; w++) out[warp * NW + w] = sc * acc[w];
    }
}

extern "C" void kernel_launch(void* const* d_in, const int* in_sizes, int n_in,
                              void* d_out, int out_size) {
    const float* query = nullptr;
    const float* support = nullptr;
    const int* labels = nullptr;
    for (int i = 0; i < n_in; i++) {
        if (in_sizes[i] == NQ * DDIM) query = (const float*)d_in[i];
        else if (in_sizes[i] == NS * DDIM) support = (const float*)d_in[i];
        else if (in_sizes[i] == NS) labels = (const int*)d_in[i];
    }
    const float* scale = (const float*)d_in[n_in - 1];
    float* out = (float*)d_out;

    static int smem_set = 0;
    if (!smem_set) {
        cudaFuncSetAttribute(k_ipm, cudaFuncAttributeMaxDynamicSharedMemorySize, SMEM_BYTES);
        smem_set = 1;
    }

    k_gemmK<<<32, 1024>>>(support);
    k_reduceK<<<16, 1024>>>();
    k_ipm<<<1, NT, SMEM_BYTES>>>(labels, out, out_size);
    k_proj<<<32, 256>>>(support);
    k_logits<<<(NQ * 32 + 255) / 256, 256>>>(query, scale, out);
}